// round 15
// baseline (speedup 1.0000x reference)
#include <cuda_runtime.h>
#include <cuda_bf16.h>
#include <cstdint>
#include <math.h>

#define NB 4
#define NS 2048
#define ND 768
#define NH 12
#define HD 64
#define KVN (NB*NH*NS*HD)
#define ACTN (NB*NS*ND)   // 6291456
#define WN (ND*ND)        // 589824

// log2(e) * 1/sqrt(64) folded into Q projection -> softmax in exp2 domain
#define QSCALE 0.1803368801111f

// Scratch (device globals — no allocation allowed)
__device__ __align__(128) __nv_bfloat16 g_qh[KVN], g_ql[KVN];
__device__ __align__(128) __nv_bfloat16 g_kh[KVN], g_kl[KVN];
__device__ __align__(128) __nv_bfloat16 g_vh[KVN], g_vl[KVN];
// pre-split activations (row-major [B*S, ND])
__device__ __align__(128) __nv_bfloat16 g_aqh[ACTN], g_aql[ACTN];
__device__ __align__(128) __nv_bfloat16 g_akh[ACTN], g_akl[ACTN];
__device__ __align__(128) __nv_bfloat16 g_avh[ACTN], g_avl[ACTN];
// pre-split weights ([ND, ND], original [k][n] layout)
__device__ __align__(128) __nv_bfloat16 g_wqh[WN], g_wql[WN];
__device__ __align__(128) __nv_bfloat16 g_wkh[WN], g_wkl[WN];
__device__ __align__(128) __nv_bfloat16 g_wvh[WN], g_wvl[WN];
__device__ __align__(128) __nv_bfloat16 g_woh[WN], g_wol[WN];
// ctx written by attention as hi/lo bf16 ([B*S, ND])
__device__ __align__(128) __nv_bfloat16 g_ch[ACTN], g_cl[ACTN];

// ---------------------------------------------------------------------------
// helpers
// ---------------------------------------------------------------------------
__device__ __forceinline__ uint32_t s2u(const void* p) {
    return (uint32_t)__cvta_generic_to_shared(p);
}
__device__ __forceinline__ void ldm4(uint32_t* r, uint32_t addr) {
    asm volatile("ldmatrix.sync.aligned.m8n8.x4.shared.b16 {%0,%1,%2,%3}, [%4];"
                 : "=r"(r[0]), "=r"(r[1]), "=r"(r[2]), "=r"(r[3]) : "r"(addr));
}
__device__ __forceinline__ void ldm4t(uint32_t* r, uint32_t addr) {
    asm volatile("ldmatrix.sync.aligned.m8n8.x4.trans.shared.b16 {%0,%1,%2,%3}, [%4];"
                 : "=r"(r[0]), "=r"(r[1]), "=r"(r[2]), "=r"(r[3]) : "r"(addr));
}
__device__ __forceinline__ void mma16816(float* c, const uint32_t* a, const uint32_t* b) {
    asm volatile("mma.sync.aligned.m16n8k16.row.col.f32.bf16.bf16.f32 "
                 "{%0,%1,%2,%3}, {%4,%5,%6,%7}, {%8,%9}, {%0,%1,%2,%3};"
                 : "+f"(c[0]), "+f"(c[1]), "+f"(c[2]), "+f"(c[3])
                 : "r"(a[0]), "r"(a[1]), "r"(a[2]), "r"(a[3]), "r"(b[0]), "r"(b[1]));
}
__device__ __forceinline__ void cp16(uint32_t saddr, const void* g) {
    asm volatile("cp.async.cg.shared.global [%0], [%1], 16;" :: "r"(saddr), "l"(g) : "memory");
}
__device__ __forceinline__ float ex2(float x) {
    float r; asm("ex2.approx.ftz.f32 %0, %1;" : "=f"(r) : "f"(x)); return r;
}
// split (x,y) into packed bf16x2 hi and lo (x in low half)
__device__ __forceinline__ void split2(float x, float y, uint32_t& hi, uint32_t& lo) {
    __nv_bfloat162 h = __floats2bfloat162_rn(x, y);
    __nv_bfloat162 l = __floats2bfloat162_rn(x - __low2float(h), y - __high2float(h));
    hi = *(uint32_t*)&h;
    lo = *(uint32_t*)&l;
}

// ---------------------------------------------------------------------------
// merged elementwise fp32 -> bf16 hi/lo split for the 3 activations (grid.z)
// ---------------------------------------------------------------------------
__global__ void __launch_bounds__(256) split3_kernel(
    const float* __restrict__ q, const float* __restrict__ k,
    const float* __restrict__ v, int n4)
{
    int i = blockIdx.x * 256 + threadIdx.x;
    if (i >= n4) return;
    const int z = blockIdx.z;
    const float* src = (z == 0) ? q : (z == 1) ? k : v;
    __nv_bfloat16* dh = (z == 0) ? g_aqh : (z == 1) ? g_akh : g_avh;
    __nv_bfloat16* dl = (z == 0) ? g_aql : (z == 1) ? g_akl : g_avl;
    float4 vv = ((const float4*)src)[i];
    uint32_t h0, l0, h1, l1;
    split2(vv.x, vv.y, h0, l0);
    split2(vv.z, vv.w, h1, l1);
    ((uint32_t*)dh)[i * 2] = h0; ((uint32_t*)dh)[i * 2 + 1] = h1;
    ((uint32_t*)dl)[i * 2] = l0; ((uint32_t*)dl)[i * 2 + 1] = l1;
}

// merged weight split (grid.z = 0..3 -> wq/wk/wv/wo), keeps [k][n] layout
__global__ void __launch_bounds__(256) wsplit4_kernel(
    const float* __restrict__ wq, const float* __restrict__ wk,
    const float* __restrict__ wv, const float* __restrict__ wo, int n4)
{
    int i = blockIdx.x * 256 + threadIdx.x;
    if (i >= n4) return;
    const int z = blockIdx.z;
    const float* src = (z == 0) ? wq : (z == 1) ? wk : (z == 2) ? wv : wo;
    __nv_bfloat16* dh = (z == 0) ? g_wqh : (z == 1) ? g_wkh : (z == 2) ? g_wvh : g_woh;
    __nv_bfloat16* dl = (z == 0) ? g_wql : (z == 1) ? g_wkl : (z == 2) ? g_wvl : g_wol;
    float4 vv = ((const float4*)src)[i];
    uint32_t h0, l0, h1, l1;
    split2(vv.x, vv.y, h0, l0);
    split2(vv.z, vv.w, h1, l1);
    ((uint32_t*)dh)[i * 2] = h0; ((uint32_t*)dh)[i * 2 + 1] = h1;
    ((uint32_t*)dl)[i * 2] = l0; ((uint32_t*)dl)[i * 2 + 1] = l1;
}

// ---------------------------------------------------------------------------
// bf16x3 GEMM mainloop on pre-split inputs: pure cp.async + ldmatrix + mma.
// 128x128 C tile, 256 threads, warp tile 32x64, kblk 32, double-buffered.
// ---------------------------------------------------------------------------
#define GA_LD 40
#define GB_LD 136
#define G_AH 0
#define G_AL 5120
#define G_BH 10240
#define G_BL 14592
#define G_BUF 18944   // bf16 elems per buffer; x2 buffers = 75776 bytes

__device__ __forceinline__ void gemm_main(
    const __nv_bfloat16* __restrict__ Agh, const __nv_bfloat16* __restrict__ Agl,
    const __nv_bfloat16* __restrict__ Wgh, const __nv_bfloat16* __restrict__ Wgl,
    __nv_bfloat16* sb, int m0, int n0, float acc[2][8][4])
{
    const int t = threadIdx.x, lane = t & 31, warp = t >> 5;
    const int wm = (warp & 3) * 32, wn = (warp >> 2) * 64;
    const int g = lane >> 3;

    auto prefetch = [&](int k0, int buf) {
        __nv_bfloat16* base = sb + buf * G_BUF;
        #pragma unroll
        for (int i = 0; i < 2; i++) {
            int idx = t + i * 256;           // 512 chunks for A (128 rows x 4)
            int r = idx >> 2, ch = (idx & 3) * 8;
            cp16(s2u(base + G_AH + r * GA_LD + ch), Agh + (size_t)(m0 + r) * ND + k0 + ch);
            cp16(s2u(base + G_AL + r * GA_LD + ch), Agl + (size_t)(m0 + r) * ND + k0 + ch);
        }
        #pragma unroll
        for (int i = 0; i < 2; i++) {
            int idx = t + i * 256;           // 512 chunks for B (32 rows x 16)
            int r = idx >> 4, ch = (idx & 15) * 8;
            cp16(s2u(base + G_BH + r * GB_LD + ch), Wgh + (size_t)(k0 + r) * ND + n0 + ch);
            cp16(s2u(base + G_BL + r * GB_LD + ch), Wgl + (size_t)(k0 + r) * ND + n0 + ch);
        }
        asm volatile("cp.async.commit_group;" ::: "memory");
    };

    prefetch(0, 0);

    const int NK = ND / 32;  // 24
    for (int kb = 0; kb < NK; kb++) {
        if (kb + 1 < NK) {
            prefetch((kb + 1) * 32, (kb + 1) & 1);
            asm volatile("cp.async.wait_group 1;" ::: "memory");
        } else {
            asm volatile("cp.async.wait_group 0;" ::: "memory");
        }
        __syncthreads();
        const __nv_bfloat16* base = sb + (kb & 1) * G_BUF;
        #pragma unroll
        for (int ks = 0; ks < 32; ks += 16) {
            uint32_t ah[2][4], al[2][4];
            #pragma unroll
            for (int mt = 0; mt < 2; mt++) {
                uint32_t ad = s2u(base + G_AH + (wm + mt * 16 + (lane & 15)) * GA_LD
                                  + ks + (lane >> 4) * 8);
                ldm4(ah[mt], ad);
                ldm4(al[mt], ad + (G_AL - G_AH) * 2);
            }
            #pragma unroll
            for (int jg = 0; jg < 4; jg++) {
                uint32_t bd = s2u(base + G_BH + (ks + ((g & 1) << 3) + (lane & 7)) * GB_LD
                                  + wn + jg * 16 + ((g >> 1) << 3));
                uint32_t bh[4], bl[4];
                ldm4t(bh, bd);
                ldm4t(bl, bd + (G_BL - G_BH) * 2);
                #pragma unroll
                for (int mt = 0; mt < 2; mt++) {
                    #pragma unroll
                    for (int ss = 0; ss < 2; ss++) {
                        float* c = acc[mt][jg * 2 + ss];
                        mma16816(c, ah[mt], bh + ss * 2);
                        mma16816(c, ah[mt], bl + ss * 2);
                        mma16816(c, al[mt], bh + ss * 2);
                    }
                }
            }
        }
        __syncthreads();   // everyone done with this buffer before it is re-filled
    }
}

// ---------------------------------------------------------------------------
// merged QKV projection (grid z = 0/1/2 -> q/k/v), split-head bf16 hi/lo out
// ---------------------------------------------------------------------------
__global__ void __launch_bounds__(256, 2) qkv_gemm(
    const float* __restrict__ bq, const float* __restrict__ bk,
    const float* __restrict__ bv)
{
    extern __shared__ char smraw[];
    __nv_bfloat16* sb = reinterpret_cast<__nv_bfloat16*>(smraw);

    const int z = blockIdx.z;
    const __nv_bfloat16* Agh = (z == 0) ? g_aqh : (z == 1) ? g_akh : g_avh;
    const __nv_bfloat16* Agl = (z == 0) ? g_aql : (z == 1) ? g_akl : g_avl;
    const __nv_bfloat16* Wgh = (z == 0) ? g_wqh : (z == 1) ? g_wkh : g_wvh;
    const __nv_bfloat16* Wgl = (z == 0) ? g_wql : (z == 1) ? g_wkl : g_wvl;
    const float* bias = (z == 0) ? bq : (z == 1) ? bk : bv;
    __nv_bfloat16* oh = (z == 0) ? g_qh : (z == 1) ? g_kh : g_vh;
    __nv_bfloat16* ol = (z == 0) ? g_ql : (z == 1) ? g_kl : g_vl;
    const float sc = (z == 0) ? QSCALE : 1.0f;

    const int m0 = blockIdx.y * 128, n0 = blockIdx.x * 128;

    float acc[2][8][4];
    #pragma unroll
    for (int i = 0; i < 2; i++)
        #pragma unroll
        for (int j = 0; j < 8; j++)
            #pragma unroll
            for (int c = 0; c < 4; c++) acc[i][j][c] = 0.f;

    gemm_main(Agh, Agl, Wgh, Wgl, sb, m0, n0, acc);

    const int lane = threadIdx.x & 31, warp = threadIdx.x >> 5;
    const int wm = (warp & 3) * 32, wn = (warp >> 2) * 64;
    #pragma unroll
    for (int mt = 0; mt < 2; mt++) {
        #pragma unroll
        for (int j = 0; j < 8; j++) {
            int col = n0 + wn + j * 8 + (lane & 3) * 2;
            float b0 = __ldg(bias + col), b1 = __ldg(bias + col + 1);
            #pragma unroll
            for (int rr = 0; rr < 2; rr++) {
                int m = m0 + wm + mt * 16 + (lane >> 2) + rr * 8;
                float x = (acc[mt][j][rr * 2] + b0) * sc;
                float y = (acc[mt][j][rr * 2 + 1] + b1) * sc;
                int bb = m >> 11, s = m & (NS - 1);
                int hh = col >> 6, d = col & 63;
                size_t idx = (((size_t)(bb * NH + hh)) * NS + s) * HD + d;
                uint32_t hv, lv;
                split2(x, y, hv, lv);
                *(uint32_t*)(oh + idx) = hv;
                *(uint32_t*)(ol + idx) = lv;
            }
        }
    }
}

// ---------------------------------------------------------------------------
// output projection: ctx(bf16 hi/lo) @ wo + bo -> fp32 out
// ---------------------------------------------------------------------------
__global__ void __launch_bounds__(256, 2) out_gemm(
    const float* __restrict__ bias, float* __restrict__ out)
{
    extern __shared__ char smraw[];
    __nv_bfloat16* sb = reinterpret_cast<__nv_bfloat16*>(smraw);
    const int m0 = blockIdx.y * 128, n0 = blockIdx.x * 128;

    float acc[2][8][4];
    #pragma unroll
    for (int i = 0; i < 2; i++)
        #pragma unroll
        for (int j = 0; j < 8; j++)
            #pragma unroll
            for (int c = 0; c < 4; c++) acc[i][j][c] = 0.f;

    gemm_main(g_ch, g_cl, g_woh, g_wol, sb, m0, n0, acc);

    const int lane = threadIdx.x & 31, warp = threadIdx.x >> 5;
    const int wm = (warp & 3) * 32, wn = (warp >> 2) * 64;
    #pragma unroll
    for (int mt = 0; mt < 2; mt++) {
        #pragma unroll
        for (int j = 0; j < 8; j++) {
            int col = n0 + wn + j * 8 + (lane & 3) * 2;
            float b0 = __ldg(bias + col), b1 = __ldg(bias + col + 1);
            #pragma unroll
            for (int rr = 0; rr < 2; rr++) {
                int m = m0 + wm + mt * 16 + (lane >> 2) + rr * 8;
                *(float2*)&out[(size_t)m * ND + col] =
                    make_float2(acc[mt][j][rr * 2] + b0, acc[mt][j][rr * 2 + 1] + b1);
            }
        }
    }
}

// ---------------------------------------------------------------------------
// Flash attention, bf16x3 mma, no-max softmax, Q FRAGMENTS HOISTED TO
// REGISTERS (Q is loop-invariant; loading it via ldmatrix every k-tile was
// ~29% of mainloop LDSM traffic, and L1 was 49% busy). 32 regs of Q frags,
// zero Q ldmatrix in the mainloop.
// Block = (b, h, 128 q-rows), 8 warps, 2 CTAs/SM.
// ---------------------------------------------------------------------------
#define AT_LD 72
#define AT_QH 0
#define AT_QL 9216
#define AT_KV0 18432
#define AT_KBUF 18432   // per buffer: Kh 0, Kl 4608, Vh 9216, Vl 13824 (elems)

__global__ void __launch_bounds__(256, 2) attn_kernel()
{
    extern __shared__ char smraw2[];
    __nv_bfloat16* sb = reinterpret_cast<__nv_bfloat16*>(smraw2);

    const int t = threadIdx.x, lane = t & 31, warp = t >> 5;
    const int qt = blockIdx.x, hh = blockIdx.y, bb = blockIdx.z;
    const size_t hoff = ((size_t)(bb * NH + hh)) * NS * HD;
    const __nv_bfloat16* pqh = g_qh + hoff + (size_t)qt * 128 * HD;
    const __nv_bfloat16* pql = g_ql + hoff + (size_t)qt * 128 * HD;
    const __nv_bfloat16* pkh = g_kh + hoff;
    const __nv_bfloat16* pkl = g_kl + hoff;
    const __nv_bfloat16* pvh = g_vh + hoff;
    const __nv_bfloat16* pvl = g_vl + hoff;
    const int g = lane >> 3;
    const int mrow = warp * 16;

    auto prefetch = [&](int jt, int buf) {
        __nv_bfloat16* kb = sb + AT_KV0 + buf * AT_KBUF;
        #pragma unroll
        for (int i = 0; i < 8; i++) {
            int idx = t + i * 256;
            int arr = idx >> 9, id = idx & 511;
            int r = id >> 3, c8 = (id & 7) * 8;
            const __nv_bfloat16* src = (arr == 0) ? pkh : (arr == 1) ? pkl
                                      : (arr == 2) ? pvh : pvl;
            cp16(s2u(kb + arr * 4608 + r * AT_LD + c8),
                 src + (size_t)(jt * 64 + r) * HD + c8);
        }
        asm volatile("cp.async.commit_group;" ::: "memory");
    };

    prefetch(0, 0);   // async; overlaps with Q staging below

    // stage Q tile (128 x 64, hi+lo) in smem once
    #pragma unroll
    for (int i = 0; i < 8; i++) {
        int idx = t + i * 256;
        int arr = idx >> 10, id = idx & 1023;
        int r = id >> 3, c8 = (id & 7) * 8;
        const __nv_bfloat16* src = arr ? pql : pqh;
        __nv_bfloat16* dst = sb + (arr ? AT_QL : AT_QH);
        *(float4*)(dst + r * AT_LD + c8) = *(const float4*)(src + (size_t)r * HD + c8);
    }
    __syncthreads();

    // hoist Q fragments to registers (loop-invariant): 4 ks-steps x (hi,lo) x 4
    uint32_t qfh[4][4], qfl[4][4];
    #pragma unroll
    for (int ks4 = 0; ks4 < 4; ks4++) {
        uint32_t qad = s2u(sb + AT_QH + (mrow + (lane & 15)) * AT_LD
                           + ks4 * 16 + (lane >> 4) * 8);
        ldm4(qfh[ks4], qad);
        ldm4(qfl[ks4], qad + AT_QL * 2);
    }

    float sAcc[8][4], o[8][4];
    #pragma unroll
    for (int j = 0; j < 8; j++)
        #pragma unroll
        for (int c = 0; c < 4; c++) o[j][c] = 0.f;
    float lr0 = 0.f, lr1 = 0.f;   // per-thread partial row sums (lane-quad slices)

    const int NKT = NS / 64;  // 32
    for (int jt = 0; jt < NKT; jt++) {
        if (jt + 1 < NKT) {
            prefetch(jt + 1, (jt + 1) & 1);
            asm volatile("cp.async.wait_group 1;" ::: "memory");
        } else {
            asm volatile("cp.async.wait_group 0;" ::: "memory");
        }
        __syncthreads();

        const __nv_bfloat16* kvb = sb + AT_KV0 + (jt & 1) * AT_KBUF;
        const __nv_bfloat16* Kh = kvb;
        const __nv_bfloat16* Vh = kvb + 9216;

        // ---- S = Q K^T  (Q frags from registers; QSCALE folded into Q)
        #pragma unroll
        for (int j = 0; j < 8; j++)
            #pragma unroll
            for (int c = 0; c < 4; c++) sAcc[j][c] = 0.f;

        #pragma unroll
        for (int ks4 = 0; ks4 < 4; ks4++) {
            #pragma unroll
            for (int jg = 0; jg < 4; jg++) {
                uint32_t kad = s2u(Kh + (jg * 16 + ((g >> 1) << 3) + (lane & 7)) * AT_LD
                                   + ks4 * 16 + ((g & 1) << 3));
                uint32_t kh4[4], kl4[4];
                ldm4(kh4, kad);
                ldm4(kl4, kad + 4608 * 2);
                #pragma unroll
                for (int ss = 0; ss < 2; ss++) {
                    float* c = sAcc[jg * 2 + ss];
                    mma16816(c, qfh[ks4], kh4 + ss * 2);
                    mma16816(c, qfh[ks4], kl4 + ss * 2);
                    mma16816(c, qfl[ks4], kh4 + ss * 2);
                }
            }
        }

        // ---- no-max softmax: p = exp2(s); per-thread partial sums
        #pragma unroll
        for (int j = 0; j < 8; j++) {
            sAcc[j][0] = ex2(sAcc[j][0]); lr0 += sAcc[j][0];
            sAcc[j][1] = ex2(sAcc[j][1]); lr0 += sAcc[j][1];
            sAcc[j][2] = ex2(sAcc[j][2]); lr1 += sAcc[j][2];
            sAcc[j][3] = ex2(sAcc[j][3]); lr1 += sAcc[j][3];
        }

        // ---- O += P V   (P split inside kc loop; no rescaling needed)
        #pragma unroll
        for (int kc = 0; kc < 4; kc++) {
            uint32_t ph[4], pl[4];
            split2(sAcc[2*kc][0],   sAcc[2*kc][1],   ph[0], pl[0]);
            split2(sAcc[2*kc][2],   sAcc[2*kc][3],   ph[1], pl[1]);
            split2(sAcc[2*kc+1][0], sAcc[2*kc+1][1], ph[2], pl[2]);
            split2(sAcc[2*kc+1][2], sAcc[2*kc+1][3], ph[3], pl[3]);
            #pragma unroll
            for (int jg = 0; jg < 4; jg++) {
                uint32_t vad = s2u(Vh + (kc * 16 + ((g & 1) << 3) + (lane & 7)) * AT_LD
                                   + jg * 16 + ((g >> 1) << 3));
                uint32_t vh4[4], vl4[4];
                ldm4t(vh4, vad);
                ldm4t(vl4, vad + 4608 * 2);
                #pragma unroll
                for (int ss = 0; ss < 2; ss++) {
                    float* c = o[jg * 2 + ss];
                    mma16816(c, ph, vh4 + ss * 2);
                    mma16816(c, ph, vl4 + ss * 2);
                    mma16816(c, pl, vh4 + ss * 2);
                }
            }
        }
        __syncthreads();
    }

    // epilogue: reduce row sums across the lane quad ONCE, normalize, write ctx
    lr0 += __shfl_xor_sync(0xffffffffu, lr0, 1);
    lr0 += __shfl_xor_sync(0xffffffffu, lr0, 2);
    lr1 += __shfl_xor_sync(0xffffffffu, lr1, 1);
    lr1 += __shfl_xor_sync(0xffffffffu, lr1, 2);
    float inv0 = 1.f / lr0, inv1 = 1.f / lr1;
    #pragma unroll
    for (int j = 0; j < 8; j++) {
        int col = hh * HD + j * 8 + (lane & 3) * 2;
        int r0 = qt * 128 + mrow + (lane >> 2);
        uint32_t hv, lv;
        split2(o[j][0] * inv0, o[j][1] * inv0, hv, lv);
        size_t i0 = ((size_t)(bb * NS + r0)) * ND + col;
        *(uint32_t*)(g_ch + i0) = hv;
        *(uint32_t*)(g_cl + i0) = lv;
        split2(o[j][2] * inv1, o[j][3] * inv1, hv, lv);
        size_t i1 = ((size_t)(bb * NS + r0 + 8)) * ND + col;
        *(uint32_t*)(g_ch + i1) = hv;
        *(uint32_t*)(g_cl + i1) = lv;
    }
}

// ---------------------------------------------------------------------------
extern "C" void kernel_launch(void* const* d_in, const int* in_sizes, int n_in,
                              void* d_out, int out_size)
{
    const float* query = (const float*)d_in[0];
    const float* key   = (const float*)d_in[1];
    const float* value = (const float*)d_in[2];
    const float* wq = (const float*)d_in[3];
    const float* bq = (const float*)d_in[4];
    const float* wk = (const float*)d_in[5];
    const float* bk = (const float*)d_in[6];
    const float* wv = (const float*)d_in[7];
    const float* bv = (const float*)d_in[8];
    const float* wo = (const float*)d_in[9];
    const float* bo = (const float*)d_in[10];
    float* out = (float*)d_out;

    const int gemm_smem = 2 * G_BUF * 2;                  // 75776 B
    const int attn_smem = (AT_KV0 + 2 * AT_KBUF) * 2;     // 110592 B
    cudaFuncSetAttribute(qkv_gemm,
                         cudaFuncAttributeMaxDynamicSharedMemorySize, gemm_smem);
    cudaFuncSetAttribute(out_gemm,
                         cudaFuncAttributeMaxDynamicSharedMemorySize, gemm_smem);
    cudaFuncSetAttribute(attn_kernel,
                         cudaFuncAttributeMaxDynamicSharedMemorySize, attn_smem);

    // pre-split activations and weights into bf16 hi/lo (2 merged launches)
    const int act4 = ACTN / 4, w4 = WN / 4;
    split3_kernel<<<dim3(act4 / 256, 1, 3), 256>>>(query, key, value, act4);
    wsplit4_kernel<<<dim3(w4 / 256, 1, 4), 256>>>(wq, wk, wv, wo, w4);

    qkv_gemm<<<dim3(ND / 128, (NB * NS) / 128, 3), 256, gemm_smem>>>(bq, bk, bv);
    attn_kernel<<<dim3(NS / 128, NH, NB), 256, attn_smem>>>();
    out_gemm<<<dim3(ND / 128, (NB * NS) / 128), 256, gemm_smem>>>(bo, out);
}

// round 16
// speedup vs baseline: 1.1061x; 1.1061x over previous
#include <cuda_runtime.h>
#include <cuda_bf16.h>
#include <cuda_fp16.h>
#include <cstdint>
#include <math.h>

#define NB 4
#define NS 2048
#define ND 768
#define NH 12
#define HD 64
#define KVN (NB*NH*NS*HD)
#define ACTN (NB*NS*ND)   // 6291456
#define WN (ND*ND)        // 589824

// log2(e) * 1/sqrt(64) folded into Q projection -> softmax in exp2 domain
#define QSCALE 0.1803368801111f

// Scratch (device globals — no allocation allowed)
__device__ __align__(128) __nv_bfloat16 g_qh[KVN], g_ql[KVN];
__device__ __align__(128) __nv_bfloat16 g_kh[KVN], g_kl[KVN];
// V stored as fp16 hi/lo (PV mma runs in fp16)
__device__ __align__(128) __half g_vh[KVN], g_vl[KVN];
// pre-split activations (row-major [B*S, ND])
__device__ __align__(128) __nv_bfloat16 g_aqh[ACTN], g_aql[ACTN];
__device__ __align__(128) __nv_bfloat16 g_akh[ACTN], g_akl[ACTN];
__device__ __align__(128) __nv_bfloat16 g_avh[ACTN], g_avl[ACTN];
// pre-split weights ([ND, ND], original [k][n] layout)
__device__ __align__(128) __nv_bfloat16 g_wqh[WN], g_wql[WN];
__device__ __align__(128) __nv_bfloat16 g_wkh[WN], g_wkl[WN];
__device__ __align__(128) __nv_bfloat16 g_wvh[WN], g_wvl[WN];
__device__ __align__(128) __nv_bfloat16 g_woh[WN], g_wol[WN];
// ctx written by attention as hi/lo bf16 ([B*S, ND])
__device__ __align__(128) __nv_bfloat16 g_ch[ACTN], g_cl[ACTN];

// ---------------------------------------------------------------------------
// helpers
// ---------------------------------------------------------------------------
__device__ __forceinline__ uint32_t s2u(const void* p) {
    return (uint32_t)__cvta_generic_to_shared(p);
}
__device__ __forceinline__ void ldm4(uint32_t* r, uint32_t addr) {
    asm volatile("ldmatrix.sync.aligned.m8n8.x4.shared.b16 {%0,%1,%2,%3}, [%4];"
                 : "=r"(r[0]), "=r"(r[1]), "=r"(r[2]), "=r"(r[3]) : "r"(addr));
}
__device__ __forceinline__ void ldm4t(uint32_t* r, uint32_t addr) {
    asm volatile("ldmatrix.sync.aligned.m8n8.x4.trans.shared.b16 {%0,%1,%2,%3}, [%4];"
                 : "=r"(r[0]), "=r"(r[1]), "=r"(r[2]), "=r"(r[3]) : "r"(addr));
}
// bf16 mma
__device__ __forceinline__ void mma16816(float* c, const uint32_t* a, const uint32_t* b) {
    asm volatile("mma.sync.aligned.m16n8k16.row.col.f32.bf16.bf16.f32 "
                 "{%0,%1,%2,%3}, {%4,%5,%6,%7}, {%8,%9}, {%0,%1,%2,%3};"
                 : "+f"(c[0]), "+f"(c[1]), "+f"(c[2]), "+f"(c[3])
                 : "r"(a[0]), "r"(a[1]), "r"(a[2]), "r"(a[3]), "r"(b[0]), "r"(b[1]));
}
// fp16 mma (same fragment layout, f32 accumulate)
__device__ __forceinline__ void mma16816h(float* c, const uint32_t* a, const uint32_t* b) {
    asm volatile("mma.sync.aligned.m16n8k16.row.col.f32.f16.f16.f32 "
                 "{%0,%1,%2,%3}, {%4,%5,%6,%7}, {%8,%9}, {%0,%1,%2,%3};"
                 : "+f"(c[0]), "+f"(c[1]), "+f"(c[2]), "+f"(c[3])
                 : "r"(a[0]), "r"(a[1]), "r"(a[2]), "r"(a[3]), "r"(b[0]), "r"(b[1]));
}
__device__ __forceinline__ void cp16(uint32_t saddr, const void* g) {
    asm volatile("cp.async.cg.shared.global [%0], [%1], 16;" :: "r"(saddr), "l"(g) : "memory");
}
__device__ __forceinline__ float ex2(float x) {
    float r; asm("ex2.approx.ftz.f32 %0, %1;" : "=f"(r) : "f"(x)); return r;
}
// split (x,y) into packed bf16x2 hi and lo (x in low half)
__device__ __forceinline__ void split2(float x, float y, uint32_t& hi, uint32_t& lo) {
    __nv_bfloat162 h = __floats2bfloat162_rn(x, y);
    __nv_bfloat162 l = __floats2bfloat162_rn(x - __low2float(h), y - __high2float(h));
    hi = *(uint32_t*)&h;
    lo = *(uint32_t*)&l;
}
// split (x,y) into packed fp16x2 hi and lo
__device__ __forceinline__ void split2h(float x, float y, uint32_t& hi, uint32_t& lo) {
    __half2 h = __floats2half2_rn(x, y);
    __half2 l = __floats2half2_rn(x - __low2float(h), y - __high2float(h));
    hi = *(uint32_t*)&h;
    lo = *(uint32_t*)&l;
}
// pack two fp32 into fp16x2
__device__ __forceinline__ uint32_t packh2(float x, float y) {
    __half2 h = __floats2half2_rn(x, y);
    return *(uint32_t*)&h;
}

// ---------------------------------------------------------------------------
// merged elementwise fp32 -> bf16 hi/lo split for the 3 activations (grid.z)
// ---------------------------------------------------------------------------
__global__ void __launch_bounds__(256) split3_kernel(
    const float* __restrict__ q, const float* __restrict__ k,
    const float* __restrict__ v, int n4)
{
    int i = blockIdx.x * 256 + threadIdx.x;
    if (i >= n4) return;
    const int z = blockIdx.z;
    const float* src = (z == 0) ? q : (z == 1) ? k : v;
    __nv_bfloat16* dh = (z == 0) ? g_aqh : (z == 1) ? g_akh : g_avh;
    __nv_bfloat16* dl = (z == 0) ? g_aql : (z == 1) ? g_akl : g_avl;
    float4 vv = ((const float4*)src)[i];
    uint32_t h0, l0, h1, l1;
    split2(vv.x, vv.y, h0, l0);
    split2(vv.z, vv.w, h1, l1);
    ((uint32_t*)dh)[i * 2] = h0; ((uint32_t*)dh)[i * 2 + 1] = h1;
    ((uint32_t*)dl)[i * 2] = l0; ((uint32_t*)dl)[i * 2 + 1] = l1;
}

// merged weight split (grid.z = 0..3 -> wq/wk/wv/wo), keeps [k][n] layout
__global__ void __launch_bounds__(256) wsplit4_kernel(
    const float* __restrict__ wq, const float* __restrict__ wk,
    const float* __restrict__ wv, const float* __restrict__ wo, int n4)
{
    int i = blockIdx.x * 256 + threadIdx.x;
    if (i >= n4) return;
    const int z = blockIdx.z;
    const float* src = (z == 0) ? wq : (z == 1) ? wk : (z == 2) ? wv : wo;
    __nv_bfloat16* dh = (z == 0) ? g_wqh : (z == 1) ? g_wkh : (z == 2) ? g_wvh : g_woh;
    __nv_bfloat16* dl = (z == 0) ? g_wql : (z == 1) ? g_wkl : (z == 2) ? g_wvl : g_wol;
    float4 vv = ((const float4*)src)[i];
    uint32_t h0, l0, h1, l1;
    split2(vv.x, vv.y, h0, l0);
    split2(vv.z, vv.w, h1, l1);
    ((uint32_t*)dh)[i * 2] = h0; ((uint32_t*)dh)[i * 2 + 1] = h1;
    ((uint32_t*)dl)[i * 2] = l0; ((uint32_t*)dl)[i * 2 + 1] = l1;
}

// ---------------------------------------------------------------------------
// bf16x3 GEMM mainloop on pre-split inputs: pure cp.async + ldmatrix + mma.
// 128x128 C tile, 256 threads, warp tile 32x64, kblk 32, double-buffered.
// ---------------------------------------------------------------------------
#define GA_LD 40
#define GB_LD 136
#define G_AH 0
#define G_AL 5120
#define G_BH 10240
#define G_BL 14592
#define G_BUF 18944   // bf16 elems per buffer; x2 buffers = 75776 bytes

__device__ __forceinline__ void gemm_main(
    const __nv_bfloat16* __restrict__ Agh, const __nv_bfloat16* __restrict__ Agl,
    const __nv_bfloat16* __restrict__ Wgh, const __nv_bfloat16* __restrict__ Wgl,
    __nv_bfloat16* sb, int m0, int n0, float acc[2][8][4])
{
    const int t = threadIdx.x, lane = t & 31, warp = t >> 5;
    const int wm = (warp & 3) * 32, wn = (warp >> 2) * 64;
    const int g = lane >> 3;

    auto prefetch = [&](int k0, int buf) {
        __nv_bfloat16* base = sb + buf * G_BUF;
        #pragma unroll
        for (int i = 0; i < 2; i++) {
            int idx = t + i * 256;           // 512 chunks for A (128 rows x 4)
            int r = idx >> 2, ch = (idx & 3) * 8;
            cp16(s2u(base + G_AH + r * GA_LD + ch), Agh + (size_t)(m0 + r) * ND + k0 + ch);
            cp16(s2u(base + G_AL + r * GA_LD + ch), Agl + (size_t)(m0 + r) * ND + k0 + ch);
        }
        #pragma unroll
        for (int i = 0; i < 2; i++) {
            int idx = t + i * 256;           // 512 chunks for B (32 rows x 16)
            int r = idx >> 4, ch = (idx & 15) * 8;
            cp16(s2u(base + G_BH + r * GB_LD + ch), Wgh + (size_t)(k0 + r) * ND + n0 + ch);
            cp16(s2u(base + G_BL + r * GB_LD + ch), Wgl + (size_t)(k0 + r) * ND + n0 + ch);
        }
        asm volatile("cp.async.commit_group;" ::: "memory");
    };

    prefetch(0, 0);

    const int NK = ND / 32;  // 24
    for (int kb = 0; kb < NK; kb++) {
        if (kb + 1 < NK) {
            prefetch((kb + 1) * 32, (kb + 1) & 1);
            asm volatile("cp.async.wait_group 1;" ::: "memory");
        } else {
            asm volatile("cp.async.wait_group 0;" ::: "memory");
        }
        __syncthreads();
        const __nv_bfloat16* base = sb + (kb & 1) * G_BUF;
        #pragma unroll
        for (int ks = 0; ks < 32; ks += 16) {
            uint32_t ah[2][4], al[2][4];
            #pragma unroll
            for (int mt = 0; mt < 2; mt++) {
                uint32_t ad = s2u(base + G_AH + (wm + mt * 16 + (lane & 15)) * GA_LD
                                  + ks + (lane >> 4) * 8);
                ldm4(ah[mt], ad);
                ldm4(al[mt], ad + (G_AL - G_AH) * 2);
            }
            #pragma unroll
            for (int jg = 0; jg < 4; jg++) {
                uint32_t bd = s2u(base + G_BH + (ks + ((g & 1) << 3) + (lane & 7)) * GB_LD
                                  + wn + jg * 16 + ((g >> 1) << 3));
                uint32_t bh[4], bl[4];
                ldm4t(bh, bd);
                ldm4t(bl, bd + (G_BL - G_BH) * 2);
                #pragma unroll
                for (int mt = 0; mt < 2; mt++) {
                    #pragma unroll
                    for (int ss = 0; ss < 2; ss++) {
                        float* c = acc[mt][jg * 2 + ss];
                        mma16816(c, ah[mt], bh + ss * 2);
                        mma16816(c, ah[mt], bl + ss * 2);
                        mma16816(c, al[mt], bh + ss * 2);
                    }
                }
            }
        }
        __syncthreads();   // everyone done with this buffer before it is re-filled
    }
}

// ---------------------------------------------------------------------------
// merged QKV projection (grid z = 0/1/2 -> q/k/v), split-head hi/lo out.
// q/k stored bf16 (QK mma is bf16x3); v stored fp16 (PV mma is fp16).
// ---------------------------------------------------------------------------
__global__ void __launch_bounds__(256, 2) qkv_gemm(
    const float* __restrict__ bq, const float* __restrict__ bk,
    const float* __restrict__ bv)
{
    extern __shared__ char smraw[];
    __nv_bfloat16* sb = reinterpret_cast<__nv_bfloat16*>(smraw);

    const int z = blockIdx.z;
    const __nv_bfloat16* Agh = (z == 0) ? g_aqh : (z == 1) ? g_akh : g_avh;
    const __nv_bfloat16* Agl = (z == 0) ? g_aql : (z == 1) ? g_akl : g_avl;
    const __nv_bfloat16* Wgh = (z == 0) ? g_wqh : (z == 1) ? g_wkh : g_wvh;
    const __nv_bfloat16* Wgl = (z == 0) ? g_wql : (z == 1) ? g_wkl : g_wvl;
    const float* bias = (z == 0) ? bq : (z == 1) ? bk : bv;
    const float sc = (z == 0) ? QSCALE : 1.0f;

    const int m0 = blockIdx.y * 128, n0 = blockIdx.x * 128;

    float acc[2][8][4];
    #pragma unroll
    for (int i = 0; i < 2; i++)
        #pragma unroll
        for (int j = 0; j < 8; j++)
            #pragma unroll
            for (int c = 0; c < 4; c++) acc[i][j][c] = 0.f;

    gemm_main(Agh, Agl, Wgh, Wgl, sb, m0, n0, acc);

    const int lane = threadIdx.x & 31, warp = threadIdx.x >> 5;
    const int wm = (warp & 3) * 32, wn = (warp >> 2) * 64;
    #pragma unroll
    for (int mt = 0; mt < 2; mt++) {
        #pragma unroll
        for (int j = 0; j < 8; j++) {
            int col = n0 + wn + j * 8 + (lane & 3) * 2;
            float b0 = __ldg(bias + col), b1 = __ldg(bias + col + 1);
            #pragma unroll
            for (int rr = 0; rr < 2; rr++) {
                int m = m0 + wm + mt * 16 + (lane >> 2) + rr * 8;
                float x = (acc[mt][j][rr * 2] + b0) * sc;
                float y = (acc[mt][j][rr * 2 + 1] + b1) * sc;
                int bb = m >> 11, s = m & (NS - 1);
                int hh = col >> 6, d = col & 63;
                size_t idx = (((size_t)(bb * NH + hh)) * NS + s) * HD + d;
                uint32_t hv, lv;
                if (z == 2) {   // V -> fp16 hi/lo
                    split2h(x, y, hv, lv);
                    *(uint32_t*)(g_vh + idx) = hv;
                    *(uint32_t*)(g_vl + idx) = lv;
                } else {        // Q/K -> bf16 hi/lo
                    split2(x, y, hv, lv);
                    __nv_bfloat16* oh = (z == 0) ? g_qh : g_kh;
                    __nv_bfloat16* ol = (z == 0) ? g_ql : g_kl;
                    *(uint32_t*)(oh + idx) = hv;
                    *(uint32_t*)(ol + idx) = lv;
                }
            }
        }
    }
}

// ---------------------------------------------------------------------------
// output projection: ctx(bf16 hi/lo) @ wo + bo -> fp32 out
// ---------------------------------------------------------------------------
__global__ void __launch_bounds__(256, 2) out_gemm(
    const float* __restrict__ bias, float* __restrict__ out)
{
    extern __shared__ char smraw[];
    __nv_bfloat16* sb = reinterpret_cast<__nv_bfloat16*>(smraw);
    const int m0 = blockIdx.y * 128, n0 = blockIdx.x * 128;

    float acc[2][8][4];
    #pragma unroll
    for (int i = 0; i < 2; i++)
        #pragma unroll
        for (int j = 0; j < 8; j++)
            #pragma unroll
            for (int c = 0; c < 4; c++) acc[i][j][c] = 0.f;

    gemm_main(g_ch, g_cl, g_woh, g_wol, sb, m0, n0, acc);

    const int lane = threadIdx.x & 31, warp = threadIdx.x >> 5;
    const int wm = (warp & 3) * 32, wn = (warp >> 2) * 64;
    #pragma unroll
    for (int mt = 0; mt < 2; mt++) {
        #pragma unroll
        for (int j = 0; j < 8; j++) {
            int col = n0 + wn + j * 8 + (lane & 3) * 2;
            float b0 = __ldg(bias + col), b1 = __ldg(bias + col + 1);
            #pragma unroll
            for (int rr = 0; rr < 2; rr++) {
                int m = m0 + wm + mt * 16 + (lane >> 2) + rr * 8;
                *(float2*)&out[(size_t)m * ND + col] =
                    make_float2(acc[mt][j][rr * 2] + b0, acc[mt][j][rr * 2 + 1] + b1);
            }
        }
    }
}

// ---------------------------------------------------------------------------
// Flash attention: bf16x3 QK mma, no-max softmax, fp16 PV mma (P single-
// precision fp16 from exp results, V fp16 hi/lo -> 2 MMAs instead of 3, and
// P prep is 16 cvt instead of 16 split2). Q read from smem per tile (R14
// structure; the R15 register-hoist regressed).
// Block = (b, h, 128 q-rows), 8 warps, 2 CTAs/SM.
// ---------------------------------------------------------------------------
#define AT_LD 72
#define AT_QH 0
#define AT_QL 9216
#define AT_KV0 18432
#define AT_KBUF 18432   // per buffer: Kh 0, Kl 4608, Vh 9216, Vl 13824 (elems)

__global__ void __launch_bounds__(256, 2) attn_kernel()
{
    extern __shared__ char smraw2[];
    __nv_bfloat16* sb = reinterpret_cast<__nv_bfloat16*>(smraw2);

    const int t = threadIdx.x, lane = t & 31, warp = t >> 5;
    const int qt = blockIdx.x, hh = blockIdx.y, bb = blockIdx.z;
    const size_t hoff = ((size_t)(bb * NH + hh)) * NS * HD;
    const __nv_bfloat16* pqh = g_qh + hoff + (size_t)qt * 128 * HD;
    const __nv_bfloat16* pql = g_ql + hoff + (size_t)qt * 128 * HD;
    const __nv_bfloat16* pkh = g_kh + hoff;
    const __nv_bfloat16* pkl = g_kl + hoff;
    const __half* pvh = g_vh + hoff;
    const __half* pvl = g_vl + hoff;
    const int g = lane >> 3;

    // Q tile (128 x 64, hi+lo)
    #pragma unroll
    for (int i = 0; i < 8; i++) {
        int idx = t + i * 256;
        int arr = idx >> 10, id = idx & 1023;
        int r = id >> 3, c8 = (id & 7) * 8;
        const __nv_bfloat16* src = arr ? pql : pqh;
        __nv_bfloat16* dst = sb + (arr ? AT_QL : AT_QH);
        *(float4*)(dst + r * AT_LD + c8) = *(const float4*)(src + (size_t)r * HD + c8);
    }

    auto prefetch = [&](int jt, int buf) {
        __nv_bfloat16* kb = sb + AT_KV0 + buf * AT_KBUF;
        #pragma unroll
        for (int i = 0; i < 8; i++) {
            int idx = t + i * 256;
            int arr = idx >> 9, id = idx & 511;
            int r = id >> 3, c8 = (id & 7) * 8;
            const void* src = (arr == 0) ? (const void*)(pkh + (size_t)(jt * 64 + r) * HD + c8)
                            : (arr == 1) ? (const void*)(pkl + (size_t)(jt * 64 + r) * HD + c8)
                            : (arr == 2) ? (const void*)(pvh + (size_t)(jt * 64 + r) * HD + c8)
                                         : (const void*)(pvl + (size_t)(jt * 64 + r) * HD + c8);
            cp16(s2u(kb + arr * 4608 + r * AT_LD + c8), src);
        }
        asm volatile("cp.async.commit_group;" ::: "memory");
    };

    float sAcc[8][4], o[8][4];
    #pragma unroll
    for (int j = 0; j < 8; j++)
        #pragma unroll
        for (int c = 0; c < 4; c++) o[j][c] = 0.f;
    float lr0 = 0.f, lr1 = 0.f;   // per-thread partial row sums (lane-quad slices)

    const int mrow = warp * 16;

    prefetch(0, 0);

    const int NKT = NS / 64;  // 32
    for (int jt = 0; jt < NKT; jt++) {
        if (jt + 1 < NKT) {
            prefetch(jt + 1, (jt + 1) & 1);
            asm volatile("cp.async.wait_group 1;" ::: "memory");
        } else {
            asm volatile("cp.async.wait_group 0;" ::: "memory");
        }
        __syncthreads();

        const __nv_bfloat16* kvb = sb + AT_KV0 + (jt & 1) * AT_KBUF;
        const __nv_bfloat16* Kh = kvb;
        const __nv_bfloat16* Vh = kvb + 9216;   // fp16 bits, b16 loads

        // ---- S = Q K^T  (QSCALE folded into Q; exp2 domain)
        #pragma unroll
        for (int j = 0; j < 8; j++)
            #pragma unroll
            for (int c = 0; c < 4; c++) sAcc[j][c] = 0.f;

        #pragma unroll
        for (int ks = 0; ks < 64; ks += 16) {
            uint32_t qh4[4], ql4[4];
            uint32_t qad = s2u(sb + AT_QH + (mrow + (lane & 15)) * AT_LD
                               + ks + (lane >> 4) * 8);
            ldm4(qh4, qad);
            ldm4(ql4, qad + AT_QL * 2);
            #pragma unroll
            for (int jg = 0; jg < 4; jg++) {
                uint32_t kad = s2u(Kh + (jg * 16 + ((g >> 1) << 3) + (lane & 7)) * AT_LD
                                   + ks + ((g & 1) << 3));
                uint32_t kh4[4], kl4[4];
                ldm4(kh4, kad);
                ldm4(kl4, kad + 4608 * 2);
                #pragma unroll
                for (int ss = 0; ss < 2; ss++) {
                    float* c = sAcc[jg * 2 + ss];
                    mma16816(c, qh4, kh4 + ss * 2);
                    mma16816(c, qh4, kl4 + ss * 2);
                    mma16816(c, ql4, kh4 + ss * 2);
                }
            }
        }

        // ---- no-max softmax: p = exp2(s); per-thread partial sums
        #pragma unroll
        for (int j = 0; j < 8; j++) {
            sAcc[j][0] = ex2(sAcc[j][0]); lr0 += sAcc[j][0];
            sAcc[j][1] = ex2(sAcc[j][1]); lr0 += sAcc[j][1];
            sAcc[j][2] = ex2(sAcc[j][2]); lr1 += sAcc[j][2];
            sAcc[j][3] = ex2(sAcc[j][3]); lr1 += sAcc[j][3];
        }

        // ---- O += P V   (P fp16 single, V fp16 hi/lo -> 2 MMAs)
        #pragma unroll
        for (int kc = 0; kc < 4; kc++) {
            uint32_t ph[4];
            ph[0] = packh2(sAcc[2*kc][0],   sAcc[2*kc][1]);
            ph[1] = packh2(sAcc[2*kc][2],   sAcc[2*kc][3]);
            ph[2] = packh2(sAcc[2*kc+1][0], sAcc[2*kc+1][1]);
            ph[3] = packh2(sAcc[2*kc+1][2], sAcc[2*kc+1][3]);
            #pragma unroll
            for (int jg = 0; jg < 4; jg++) {
                uint32_t vad = s2u(Vh + (kc * 16 + ((g & 1) << 3) + (lane & 7)) * AT_LD
                                   + jg * 16 + ((g >> 1) << 3));
                uint32_t vh4[4], vl4[4];
                ldm4t(vh4, vad);
                ldm4t(vl4, vad + 4608 * 2);
                #pragma unroll
                for (int ss = 0; ss < 2; ss++) {
                    float* c = o[jg * 2 + ss];
                    mma16816h(c, ph, vh4 + ss * 2);
                    mma16816h(c, ph, vl4 + ss * 2);
                }
            }
        }
        __syncthreads();
    }

    // epilogue: reduce row sums across the lane quad ONCE, normalize, write ctx
    lr0 += __shfl_xor_sync(0xffffffffu, lr0, 1);
    lr0 += __shfl_xor_sync(0xffffffffu, lr0, 2);
    lr1 += __shfl_xor_sync(0xffffffffu, lr1, 1);
    lr1 += __shfl_xor_sync(0xffffffffu, lr1, 2);
    float inv0 = 1.f / lr0, inv1 = 1.f / lr1;
    #pragma unroll
    for (int j = 0; j < 8; j++) {
        int col = hh * HD + j * 8 + (lane & 3) * 2;
        int r0 = qt * 128 + mrow + (lane >> 2);
        uint32_t hv, lv;
        split2(o[j][0] * inv0, o[j][1] * inv0, hv, lv);
        size_t i0 = ((size_t)(bb * NS + r0)) * ND + col;
        *(uint32_t*)(g_ch + i0) = hv;
        *(uint32_t*)(g_cl + i0) = lv;
        split2(o[j][2] * inv1, o[j][3] * inv1, hv, lv);
        size_t i1 = ((size_t)(bb * NS + r0 + 8)) * ND + col;
        *(uint32_t*)(g_ch + i1) = hv;
        *(uint32_t*)(g_cl + i1) = lv;
    }
}

// ---------------------------------------------------------------------------
extern "C" void kernel_launch(void* const* d_in, const int* in_sizes, int n_in,
                              void* d_out, int out_size)
{
    const float* query = (const float*)d_in[0];
    const float* key   = (const float*)d_in[1];
    const float* value = (const float*)d_in[2];
    const float* wq = (const float*)d_in[3];
    const float* bq = (const float*)d_in[4];
    const float* wk = (const float*)d_in[5];
    const float* bk = (const float*)d_in[6];
    const float* wv = (const float*)d_in[7];
    const float* bv = (const float*)d_in[8];
    const float* wo = (const float*)d_in[9];
    const float* bo = (const float*)d_in[10];
    float* out = (float*)d_out;

    const int gemm_smem = 2 * G_BUF * 2;                  // 75776 B
    const int attn_smem = (AT_KV0 + 2 * AT_KBUF) * 2;     // 110592 B
    cudaFuncSetAttribute(qkv_gemm,
                         cudaFuncAttributeMaxDynamicSharedMemorySize, gemm_smem);
    cudaFuncSetAttribute(out_gemm,
                         cudaFuncAttributeMaxDynamicSharedMemorySize, gemm_smem);
    cudaFuncSetAttribute(attn_kernel,
                         cudaFuncAttributeMaxDynamicSharedMemorySize, attn_smem);

    // pre-split activations and weights into bf16 hi/lo (2 merged launches)
    const int act4 = ACTN / 4, w4 = WN / 4;
    split3_kernel<<<dim3(act4 / 256, 1, 3), 256>>>(query, key, value, act4);
    wsplit4_kernel<<<dim3(w4 / 256, 1, 4), 256>>>(wq, wk, wv, wo, w4);

    qkv_gemm<<<dim3(ND / 128, (NB * NS) / 128, 3), 256, gemm_smem>>>(bq, bk, bv);
    attn_kernel<<<dim3(NS / 128, NH, NB), 256, attn_smem>>>();
    out_gemm<<<dim3(ND / 128, (NB * NS) / 128), 256, gemm_smem>>>(bo, out);
}